// round 13
// baseline (speedup 1.0000x reference)
#include <cuda_runtime.h>
#include <math.h>

#define Bn 2
#define CIN 64
#define CI 16
#define Hn 96
#define Wn 96
#define HWn 9216
#define PSn 7
#define Kn 100
#define WSn 21
#define NCn 441
#define NHn 24
#define NWn 24
#define Qn 576
#define S0n 4
#define SCALEF 10.0f
#define REG 27
#define REG2 729

// ------------------------- device scratch (no allocs allowed) ----------------
__device__ float g_theta[Bn * CI * HWn];
__device__ float g_phi[Bn * CI * HWn];
__device__ float g_g[Bn * CI * HWn];
__device__ float g_zimg[Bn * CI * HWn];
__device__ float g_cnt[HWn];
__device__ float g_A[CIN * CI];
__device__ float g_b2[CIN];

__device__ __forceinline__ int clampi(int v, int hi) { return min(max(v, 0), hi); }

// ------------------------- zero scratch --------------------------------------
__global__ void zero_kernel() {
    int i = blockIdx.x * blockDim.x + threadIdx.x;
    if (i < Bn * CI * HWn) g_zimg[i] = 0.0f;
    if (i < HWn) g_cnt[i] = 0.0f;
}

// ------------------------- 1x1 projections theta/phi/g -----------------------
__global__ void proj_kernel(const float* __restrict__ vid,
                            const float* __restrict__ wt, const float* __restrict__ bt,
                            const float* __restrict__ wp, const float* __restrict__ bp,
                            const float* __restrict__ wg, const float* __restrict__ bg) {
    __shared__ float sw[3 * CI * CIN];
    __shared__ float sb[3 * CI];
    int tid = threadIdx.x;
    for (int i = tid; i < CI * CIN; i += blockDim.x) {
        sw[i] = wt[i];
        sw[CI * CIN + i] = wp[i];
        sw[2 * CI * CIN + i] = wg[i];
    }
    if (tid < CI) { sb[tid] = bt[tid]; sb[CI + tid] = bp[tid]; sb[2 * CI + tid] = bg[tid]; }
    __syncthreads();

    int idx = blockIdx.x * blockDim.x + tid;
    if (idx >= Bn * HWn * 3) return;
    int grp = idx / (Bn * HWn);       // 0=theta 1=phi 2=g
    int pix = idx % (Bn * HWn);
    int b = pix / HWn, hw = pix % HWn;

    float x[CIN];
#pragma unroll
    for (int c = 0; c < CIN; c++) x[c] = vid[(b * CIN + c) * HWn + hw];

    const float* w = sw + grp * CI * CIN;
    float* dst = (grp == 0 ? g_theta : (grp == 1 ? g_phi : g_g)) + b * CI * HWn + hw;
#pragma unroll 4
    for (int o = 0; o < CI; o++) {
        float a = sb[grp * CI + o];
#pragma unroll
        for (int c = 0; c < CIN; c++) a = fmaf(w[o * CIN + c], x[c], a);
        dst[o * HWn] = a;
    }
}

// ------------------------- precompute fused epilogue weights -----------------
// A[o2,ci] = sum_c w_c33[o2, c] * w_w[c, ci];  b2[o2] = sum_c w_c33[o2,c]*b_w[c] + b_c33[o2]
__global__ void precomp_kernel(const float* __restrict__ w_w, const float* __restrict__ b_w,
                               const float* __restrict__ w_c33, const float* __restrict__ b_c33) {
    int e = blockIdx.x * blockDim.x + threadIdx.x;
    if (e < CIN * CI) {
        int o = e / CI, ci = e % CI;
        float a = 0.0f;
        for (int c = 0; c < CIN; c++) a = fmaf(w_c33[o * (2 * CIN) + c], w_w[c * CI + ci], a);
        g_A[e] = a;
    }
    if (e < CIN) {
        float a = b_c33[e];
        for (int c = 0; c < CIN; c++) a = fmaf(w_c33[e * (2 * CIN) + c], b_w[c], a);
        g_b2[e] = a;
    }
}

// ------------------------- main attention kernel -----------------------------
// One block per (batch, query). 256 threads.
__global__ void __launch_bounds__(256, 2) attn_kernel() {
    extern __shared__ float sm[];
    float* sPhi = sm;                              // 16*729
    float* sG = sPhi + CI * REG2;                  // 16*729
    float* sTheta = sG + CI * REG2;                // 784
    float* scores = sTheta + CI * 49;              // 441
    unsigned* ukeys = (unsigned*)(scores + NCn);   // 441
    float* sel_w = (float*)(ukeys + NCn);          // 100
    int* sel_r27 = (int*)(sel_w + Kn);             // 700
    int* sel_c = sel_r27 + Kn * 7;                 // 700
    unsigned* hist = (unsigned*)(sel_c + Kn * 7);  // 256

    __shared__ int s_bucket, s_above, s_eqc, s_nsel;
    __shared__ float s_sum, s_m, s_wmax[8];

    int tid = threadIdx.x;
    int bq = blockIdx.x;
    int b = bq / Qn, q = bq % Qn;
    int qi = (q / NWn) * S0n, qj = (q % NWn) * S0n;
    int row0 = min(max(qi - 13, 0), Hn - REG);
    int col0 = min(max(qj - 13, 0), Wn - REG);

    // stage phi/g neighborhoods and query theta patch
    const float* phiB = g_phi + b * CI * HWn;
    const float* gB = g_g + b * CI * HWn;
    for (int t = tid; t < CI * REG2; t += 256) {
        int c = t / REG2;
        int rr = (t % REG2) / REG;
        int cc = t % REG;
        int gi = c * HWn + (row0 + rr) * Wn + (col0 + cc);
        sPhi[t] = phiB[gi];
        sG[t] = gB[gi];
    }
    const float* thB = g_theta + b * CI * HWn;
    for (int t = tid; t < CI * 49; t += 256) {
        int c = t / 49, pi = (t % 49) / 7, pj = t % 7;
        sTheta[t] = thB[c * HWn + clampi(qi + pi - 3, Hn - 1) * Wn + clampi(qj + pj - 3, Wn - 1)];
    }
    // geometric count image (batch-independent): only b==0 blocks contribute
    if (b == 0 && tid < 49) {
        int pi = tid / 7, pj = tid % 7;
        atomicAdd(&g_cnt[clampi(qi + pi - 3, Hn - 1) * Wn + clampi(qj + pj - 3, Wn - 1)], 1.0f);
    }
    __syncthreads();

    // ---- 441 candidate scores: dot of 784-length patches, all from smem ----
    for (int cand = tid; cand < NCn; cand += 256) {
        int di = cand / WSn - 10, dj = cand % WSn - 10;
        int ci = clampi(qi + di, Hn - 1), cj = clampi(qj + dj, Wn - 1);
        int rb[7], cb[7];
#pragma unroll
        for (int p = 0; p < 7; p++) {
            rb[p] = (clampi(ci + p - 3, Hn - 1) - row0) * REG;
            cb[p] = clampi(cj + p - 3, Wn - 1) - col0;
        }
        float acc = 0.0f;
#pragma unroll 1
        for (int c = 0; c < CI; c++) {
            const float* ph = sPhi + c * REG2;
            const float* th = sTheta + c * 49;
#pragma unroll
            for (int pi = 0; pi < 7; pi++) {
                const float* prow = ph + rb[pi];
#pragma unroll
                for (int pj = 0; pj < 7; pj++)
                    acc = fmaf(th[pi * 7 + pj], prow[cb[pj]], acc);
            }
        }
        scores[cand] = acc;
        unsigned u = __float_as_uint(acc);
        ukeys[cand] = (u & 0x80000000u) ? ~u : (u | 0x80000000u);
    }
    __syncthreads();

    // ---- block max (for softmax stabilization) ----
    float lm = -3.4e38f;
    for (int i = tid; i < NCn; i += 256) lm = fmaxf(lm, scores[i]);
#pragma unroll
    for (int o = 16; o > 0; o >>= 1) lm = fmaxf(lm, __shfl_xor_sync(0xffffffffu, lm, o));
    if ((tid & 31) == 0) s_wmax[tid >> 5] = lm;
    __syncthreads();
    if (tid == 0) {
        float mm = s_wmax[0];
#pragma unroll
        for (int j = 1; j < 8; j++) mm = fmaxf(mm, s_wmax[j]);
        s_m = mm;
        s_eqc = 0;
        s_nsel = 0;
        s_sum = 0.0f;
    }

    // ---- exact 100th-largest via 4-pass radix select on monotone uint keys ----
    unsigned prefix = 0;
    int remaining = Kn;
    for (int shift = 24; shift >= 0; shift -= 8) {
        hist[tid] = 0u;
        __syncthreads();
        unsigned hm = (shift == 24) ? 0u : (0xFFFFFFFFu << (shift + 8));
        for (int i = tid; i < NCn; i += 256) {
            unsigned k = ukeys[i];
            if ((k & hm) == prefix) atomicAdd(&hist[(k >> shift) & 255u], 1u);
        }
        __syncthreads();
        if (tid == 0) {
            int cum = 0, bsel = 0;
            for (int bb = 255; bb >= 0; bb--) {
                int h = (int)hist[bb];
                if (cum + h >= remaining) { bsel = bb; break; }
                cum += h;
            }
            s_bucket = bsel;
            s_above = cum;
        }
        __syncthreads();
        prefix |= ((unsigned)s_bucket) << shift;
        remaining -= s_above;
        __syncthreads();
    }
    unsigned pivot = prefix;
    int needEq = remaining;
    float m = s_m;

    // ---- select top-100, compute exp weights, precompute patch offsets ----
    for (int i = tid; i < NCn; i += 256) {
        unsigned k = ukeys[i];
        bool take = false;
        if (k > pivot) take = true;
        else if (k == pivot) { if (atomicAdd(&s_eqc, 1) < needEq) take = true; }
        if (take) {
            int slot = atomicAdd(&s_nsel, 1);
            if (slot < Kn) {
                float e = __expf(SCALEF * (scores[i] - m));
                sel_w[slot] = e;
                atomicAdd(&s_sum, e);
                int di = i / WSn - 10, dj = i % WSn - 10;
                int ci = clampi(qi + di, Hn - 1), cj = clampi(qj + dj, Wn - 1);
#pragma unroll
                for (int p = 0; p < 7; p++) {
                    sel_r27[slot * 7 + p] = (clampi(ci + p - 3, Hn - 1) - row0) * REG;
                    sel_c[slot * 7 + p] = clampi(cj + p - 3, Wn - 1) - col0;
                }
            }
        }
    }
    __syncthreads();
    int nsel = min(s_nsel, Kn);
    float invs = 1.0f / s_sum;

    // ---- weighted patch sum + overlap-add scatter ----
    for (int d = tid; d < CI * 49; d += 256) {
        int c = d / 49, rem = d % 49, pi = rem / 7, pj = rem % 7;
        const float* gg = sG + c * REG2;
        float acc = 0.0f;
#pragma unroll 4
        for (int k = 0; k < nsel; k++)
            acc = fmaf(sel_w[k], gg[sel_r27[k * 7 + pi] + sel_c[k * 7 + pj]], acc);
        acc *= invs;
        int prr = clampi(qi + pi - 3, Hn - 1), pcc = clampi(qj + pj - 3, Wn - 1);
        atomicAdd(&g_zimg[(b * CI + c) * HWn + prr * Wn + pcc], acc);
    }
}

// ------------------------- fused output: out = A*(zimg/cnt) + w_c33_r*vid + b2
__global__ void out_kernel(const float* __restrict__ vid,
                           const float* __restrict__ wc, float* __restrict__ out) {
    __shared__ float sA[CIN * CI], sW2[CIN * CIN], sB2[CIN];
    int tid = threadIdx.x;
    for (int i = tid; i < CIN * CI; i += 256) sA[i] = g_A[i];
    for (int i = tid; i < CIN * CIN; i += 256) {
        int o = i / CIN, c = i % CIN;
        sW2[i] = wc[o * (2 * CIN) + CIN + c];
    }
    if (tid < CIN) sB2[tid] = g_b2[tid];
    __syncthreads();

    int idx = blockIdx.x * 256 + tid;
    if (idx >= Bn * HWn * 4) return;
    int grp = idx / (Bn * HWn);     // which 16 output channels
    int pix = idx % (Bn * HWn);
    int b = pix / HWn, hw = pix % HWn;

    float invc = 1.0f / fmaxf(g_cnt[hw], 1.0f);
    float zv[CI];
#pragma unroll
    for (int ci = 0; ci < CI; ci++) zv[ci] = g_zimg[(b * CI + ci) * HWn + hw] * invc;
    float x[CIN];
#pragma unroll
    for (int c = 0; c < CIN; c++) x[c] = vid[(b * CIN + c) * HWn + hw];

    int o0 = grp * 16;
#pragma unroll 4
    for (int oo = 0; oo < 16; oo++) {
        int o = o0 + oo;
        float a = sB2[o];
#pragma unroll
        for (int ci = 0; ci < CI; ci++) a = fmaf(sA[o * CI + ci], zv[ci], a);
#pragma unroll
        for (int c = 0; c < CIN; c++) a = fmaf(sW2[o * CIN + c], x[c], a);
        out[(b * CIN + o) * HWn + hw] = a;
    }
}

// ------------------------- launch --------------------------------------------
extern "C" void kernel_launch(void* const* d_in, const int* in_sizes, int n_in,
                              void* d_out, int out_size) {
    const float* vid = (const float*)d_in[0];
    const float* w_theta = (const float*)d_in[1];
    const float* b_theta = (const float*)d_in[2];
    const float* w_phi = (const float*)d_in[3];
    const float* b_phi = (const float*)d_in[4];
    const float* w_g = (const float*)d_in[5];
    const float* b_g = (const float*)d_in[6];
    const float* w_w = (const float*)d_in[7];
    const float* b_w = (const float*)d_in[8];
    const float* w_c33 = (const float*)d_in[9];
    const float* b_c33 = (const float*)d_in[10];
    float* out = (float*)d_out;

    // dynamic smem: phi + g regions, theta patch, scores, keys, sel arrays, hist
    int smem_floats = 2 * CI * REG2 + CI * 49 + NCn + NCn + Kn + 2 * Kn * 7 + 256;
    int smem = smem_floats * 4;
    cudaFuncSetAttribute(attn_kernel, cudaFuncAttributeMaxDynamicSharedMemorySize, smem);

    zero_kernel<<<(Bn * CI * HWn + 255) / 256, 256>>>();
    proj_kernel<<<(Bn * HWn * 3 + 255) / 256, 256>>>(vid, w_theta, b_theta, w_phi, b_phi, w_g, b_g);
    precomp_kernel<<<4, 256>>>(w_w, b_w, w_c33, b_c33);
    attn_kernel<<<Bn * Qn, 256, smem>>>();
    out_kernel<<<(Bn * HWn * 4 + 255) / 256, 256>>>(vid, w_c33, out);
}

// round 14
// speedup vs baseline: 1.4693x; 1.4693x over previous
#include <cuda_runtime.h>
#include <math.h>

#define Bn 2
#define CIN 64
#define CI 16
#define Hn 96
#define Wn 96
#define HWn 9216
#define PSn 7
#define Kn 100
#define WSn 21
#define NCn 441
#define NHn 24
#define NWn 24
#define Qn 576
#define S0n 4
#define SCALEF 10.0f
#define REG 27
#define REG2 729

// ------------------------- device scratch (no allocs allowed) ----------------
__device__ float g_theta[Bn * CI * HWn];
__device__ float g_phi[Bn * CI * HWn];
__device__ float g_g[Bn * CI * HWn];
__device__ float g_zimg[Bn * CI * HWn];
__device__ float g_cnt[HWn];
__device__ float g_A[CIN * CI];
__device__ float g_b2[CIN];

__device__ __forceinline__ int clampi(int v, int hi) { return min(max(v, 0), hi); }

// ------------------------- zero scratch --------------------------------------
__global__ void zero_kernel() {
    int i = blockIdx.x * blockDim.x + threadIdx.x;
    if (i < Bn * CI * HWn) g_zimg[i] = 0.0f;
    if (i < HWn) g_cnt[i] = 0.0f;
}

// ------------------------- 1x1 projections theta/phi/g -----------------------
__global__ void proj_kernel(const float* __restrict__ vid,
                            const float* __restrict__ wt, const float* __restrict__ bt,
                            const float* __restrict__ wp, const float* __restrict__ bp,
                            const float* __restrict__ wg, const float* __restrict__ bg) {
    __shared__ float sw[3 * CI * CIN];
    __shared__ float sb[3 * CI];
    int tid = threadIdx.x;
    for (int i = tid; i < CI * CIN; i += blockDim.x) {
        sw[i] = wt[i];
        sw[CI * CIN + i] = wp[i];
        sw[2 * CI * CIN + i] = wg[i];
    }
    if (tid < CI) { sb[tid] = bt[tid]; sb[CI + tid] = bp[tid]; sb[2 * CI + tid] = bg[tid]; }
    __syncthreads();

    int idx = blockIdx.x * blockDim.x + tid;
    if (idx >= Bn * HWn * 3) return;
    int grp = idx / (Bn * HWn);       // 0=theta 1=phi 2=g
    int pix = idx % (Bn * HWn);
    int b = pix / HWn, hw = pix % HWn;

    float x[CIN];
#pragma unroll
    for (int c = 0; c < CIN; c++) x[c] = vid[(b * CIN + c) * HWn + hw];

    const float* w = sw + grp * CI * CIN;
    float* dst = (grp == 0 ? g_theta : (grp == 1 ? g_phi : g_g)) + b * CI * HWn + hw;
#pragma unroll 4
    for (int o = 0; o < CI; o++) {
        float a = sb[grp * CI + o];
#pragma unroll
        for (int c = 0; c < CIN; c++) a = fmaf(w[o * CIN + c], x[c], a);
        dst[o * HWn] = a;
    }
}

// ------------------------- precompute fused epilogue weights -----------------
__global__ void precomp_kernel(const float* __restrict__ w_w, const float* __restrict__ b_w,
                               const float* __restrict__ w_c33, const float* __restrict__ b_c33) {
    int e = blockIdx.x * blockDim.x + threadIdx.x;
    if (e < CIN * CI) {
        int o = e / CI, ci = e % CI;
        float a = 0.0f;
        for (int c = 0; c < CIN; c++) a = fmaf(w_c33[o * (2 * CIN) + c], w_w[c * CI + ci], a);
        g_A[e] = a;
    }
    if (e < CIN) {
        float a = b_c33[e];
        for (int c = 0; c < CIN; c++) a = fmaf(w_c33[e * (2 * CIN) + c], b_w[c], a);
        g_b2[e] = a;
    }
}

// ------------------------- main attention kernel -----------------------------
// One block per (batch, query). 256 threads.
// smem layout (float words):
//   [0,11664)        sPhi
//   [11664,23328)    sG
//   [23328,24112)    sTheta            (dead after score phase)
//   [24112,24553)    scores            (dead after selection)
//   [24553,24994)    ukeys             (dead after selection)
//   [24994,26750)    region A:
//       score phase:  part[3*441]
//       after:        hist[256] | sel_w[100] | sel_r27[700] | sel_c[700]
//   zpart[2*784] overlays [23328,24896) during z phase
#define SMEM_WORDS 26750

__global__ void __launch_bounds__(256, 2) attn_kernel() {
    extern __shared__ float sm[];
    float* sPhi = sm;
    float* sG = sm + 11664;
    float* sTheta = sm + 23328;
    float* scores = sm + 24112;
    unsigned* ukeys = (unsigned*)(sm + 24553);
    float* part = sm + 24994;                       // 3*441 during score phase
    unsigned* hist = (unsigned*)(sm + 24994);       // after score phase
    float* sel_w = sm + 24994 + 256;
    int* sel_r27 = (int*)(sm + 24994 + 356);
    int* sel_c = (int*)(sm + 24994 + 1056);
    float* zpart = sm + 23328;                      // 2*784, z phase only

    __shared__ int s_bucket, s_above, s_eqc, s_nsel;
    __shared__ float s_sum, s_m, s_wmax[8];
    __shared__ unsigned s_scan[8];

    int tid = threadIdx.x;
    int bq = blockIdx.x;
    int b = bq / Qn, q = bq % Qn;
    int qi = (q / NWn) * S0n, qj = (q % NWn) * S0n;
    int row0 = min(max(qi - 13, 0), Hn - REG);
    int col0 = min(max(qj - 13, 0), Wn - REG);

    // ---- stage phi/g neighborhoods and query theta patch ----
    const float* phiB = g_phi + b * CI * HWn;
    const float* gB = g_g + b * CI * HWn;
    for (int t = tid; t < CI * REG2; t += 256) {
        int c = t / REG2;
        int rr = (t % REG2) / REG;
        int cc = t % REG;
        int gi = c * HWn + (row0 + rr) * Wn + (col0 + cc);
        sPhi[t] = phiB[gi];
        sG[t] = gB[gi];
    }
    const float* thB = g_theta + b * CI * HWn;
    for (int t = tid; t < CI * 49; t += 256) {
        int c = t / 49, pi = (t % 49) / 7, pj = t % 7;
        sTheta[t] = thB[c * HWn + clampi(qi + pi - 3, Hn - 1) * Wn + clampi(qj + pj - 3, Wn - 1)];
    }
    if (b == 0 && tid < 49) {
        int pi = tid / 7, pj = tid % 7;
        atomicAdd(&g_cnt[clampi(qi + pi - 3, Hn - 1) * Wn + clampi(qj + pj - 3, Wn - 1)], 1.0f);
    }
    __syncthreads();

    // ---- score phase: register-tiled 7-candidate groups ----
    // tid layout: cg = tid/63 (channel group of 4), rem = tid%63,
    //             di_idx = rem/3 (candidate row), g = rem%3 (dj group of 7)
    if (tid < 252) {
        int cg = tid / 63;
        int rem = tid % 63;
        int di_idx = rem / 3;
        int g = rem % 3;
        int dj0 = g * 7 - 10;
        int cbase = cg * 4;

        int ci = clampi(qi + di_idx - 10, Hn - 1);
        int rb[7];
#pragma unroll
        for (int p = 0; p < 7; p++) rb[p] = (clampi(ci + p - 3, Hn - 1) - row0) * REG;

        float acc[7];
#pragma unroll
        for (int t = 0; t < 7; t++) acc[t] = 0.0f;

        int base = qj + dj0;
        bool fast = (base >= 3) && (base <= 86);

        if (fast) {
            int colLo = base - 3 - col0;   // 13-wide window [colLo, colLo+12]
#pragma unroll 1
            for (int c = 0; c < 4; c++) {
                const float* thc = sTheta + (cbase + c) * 49;
                const float* phc = sPhi + (cbase + c) * REG2 + colLo;
#pragma unroll
                for (int pi = 0; pi < 7; pi++) {
                    const float* th = thc + pi * 7;
                    const float* ph = phc + rb[pi];
                    float thv[7];
#pragma unroll
                    for (int pj = 0; pj < 7; pj++) thv[pj] = th[pj];
                    float wv[13];
#pragma unroll
                    for (int x = 0; x < 13; x++) wv[x] = ph[x];
#pragma unroll
                    for (int t = 0; t < 7; t++)
#pragma unroll
                        for (int pj = 0; pj < 7; pj++)
                            acc[t] = fmaf(thv[pj], wv[t + pj], acc[t]);
                }
            }
        } else {
            // exact double-clamp fallback (border columns only)
#pragma unroll 1
            for (int t = 0; t < 7; t++) {
                int cj = clampi(qj + dj0 + t, Wn - 1);
                int cb[7];
#pragma unroll
                for (int p = 0; p < 7; p++) cb[p] = clampi(cj + p - 3, Wn - 1) - col0;
                float a = 0.0f;
#pragma unroll 1
                for (int c = 0; c < 4; c++) {
                    const float* th = sTheta + (cbase + c) * 49;
                    const float* ph = sPhi + (cbase + c) * REG2;
#pragma unroll
                    for (int pi = 0; pi < 7; pi++) {
                        const float* pr = ph + rb[pi];
#pragma unroll
                        for (int pj = 0; pj < 7; pj++)
                            a = fmaf(th[pi * 7 + pj], pr[cb[pj]], a);
                    }
                }
                acc[t] = a;
            }
        }

        // write partials: cg0 -> scores, cg1..3 -> part
#pragma unroll
        for (int t = 0; t < 7; t++) {
            int i = di_idx * 21 + g * 7 + t;
            if (cg == 0) scores[i] = acc[t];
            else part[(cg - 1) * NCn + i] = acc[t];
        }
    }
    __syncthreads();

    // ---- combine channel partials + build monotone keys ----
    for (int i = tid; i < NCn; i += 256) {
        float s = scores[i] + part[i] + part[NCn + i] + part[2 * NCn + i];
        scores[i] = s;
        unsigned u = __float_as_uint(s);
        ukeys[i] = (u & 0x80000000u) ? ~u : (u | 0x80000000u);
    }
    __syncthreads();

    // ---- block max (softmax stabilization) ----
    float lm = -3.4e38f;
    for (int i = tid; i < NCn; i += 256) lm = fmaxf(lm, scores[i]);
#pragma unroll
    for (int o = 16; o > 0; o >>= 1) lm = fmaxf(lm, __shfl_xor_sync(0xffffffffu, lm, o));
    if ((tid & 31) == 0) s_wmax[tid >> 5] = lm;
    __syncthreads();
    if (tid == 0) {
        float mm = s_wmax[0];
#pragma unroll
        for (int j = 1; j < 8; j++) mm = fmaxf(mm, s_wmax[j]);
        s_m = mm;
        s_eqc = 0;
        s_nsel = 0;
        s_sum = 0.0f;
    }

    // ---- exact 100th-largest via 4-pass radix select (parallel bucket scan) ----
    unsigned prefix = 0;
    int remaining = Kn;
    for (int shift = 24; shift >= 0; shift -= 8) {
        hist[tid] = 0u;
        __syncthreads();
        unsigned hm = (shift == 24) ? 0u : (0xFFFFFFFFu << (shift + 8));
        for (int i = tid; i < NCn; i += 256) {
            unsigned k = ukeys[i];
            if ((k & hm) == prefix) atomicAdd(&hist[(k >> shift) & 255u], 1u);
        }
        __syncthreads();
        // suffix-sum scan: tid 0 corresponds to bucket 255 (descending)
        {
            unsigned v = hist[255 - tid];
            unsigned inc = v;
#pragma unroll
            for (int o = 1; o < 32; o <<= 1) {
                unsigned n = __shfl_up_sync(0xffffffffu, inc, o);
                if ((tid & 31) >= o) inc += n;
            }
            if ((tid & 31) == 31) s_scan[tid >> 5] = inc;
            __syncthreads();
            if (tid < 8) {
                unsigned x = s_scan[tid];
#pragma unroll
                for (int o = 1; o < 8; o <<= 1) {
                    unsigned n = __shfl_up_sync(0xffu, x, o);
                    if (tid >= o) x += n;
                }
                s_scan[tid] = x;
            }
            __syncthreads();
            unsigned offs = (tid >= 32) ? s_scan[(tid >> 5) - 1] : 0u;
            unsigned incl = inc + offs;
            unsigned excl = incl - v;
            if (excl < (unsigned)remaining && incl >= (unsigned)remaining) {
                s_bucket = 255 - tid;
                s_above = (int)excl;
            }
        }
        __syncthreads();
        prefix |= ((unsigned)s_bucket) << shift;
        remaining -= s_above;
        __syncthreads();
    }
    unsigned pivot = prefix;
    int needEq = remaining;
    float m = s_m;

    // ---- select top-100, compute exp weights, precompute patch offsets ----
    for (int i = tid; i < NCn; i += 256) {
        unsigned k = ukeys[i];
        bool take = false;
        if (k > pivot) take = true;
        else if (k == pivot) { if (atomicAdd(&s_eqc, 1) < needEq) take = true; }
        if (take) {
            int slot = atomicAdd(&s_nsel, 1);
            if (slot < Kn) {
                float e = __expf(SCALEF * (scores[i] - m));
                sel_w[slot] = e;
                atomicAdd(&s_sum, e);
                int di = i / WSn - 10, dj = i % WSn - 10;
                int ci = clampi(qi + di, Hn - 1), cj = clampi(qj + dj, Wn - 1);
#pragma unroll
                for (int p = 0; p < 7; p++) {
                    sel_r27[slot * 7 + p] = (clampi(ci + p - 3, Hn - 1) - row0) * REG;
                    sel_c[slot * 7 + p] = clampi(cj + p - 3, Wn - 1) - col0;
                }
            }
        }
    }
    __syncthreads();
    int nsel = min(s_nsel, Kn);
    float invs = 1.0f / s_sum;

    // ---- weighted patch sum, thread = (c, pi, k-half), 7 pj accumulators ----
    if (tid < 224) {
        int ci_ = tid % 112;
        int ks = tid / 112;
        int c = ci_ / 7, pi = ci_ % 7;
        int half = (nsel + 1) >> 1;
        int k0 = ks * half, k1 = min(nsel, k0 + half);
        const float* gcBase = sG + c * REG2;
        float a7[7];
#pragma unroll
        for (int pj = 0; pj < 7; pj++) a7[pj] = 0.0f;
#pragma unroll 2
        for (int k = k0; k < k1; k++) {
            float w = sel_w[k];
            const float* gg = gcBase + sel_r27[k * 7 + pi];
            const int* cc = sel_c + k * 7;
#pragma unroll
            for (int pj = 0; pj < 7; pj++)
                a7[pj] = fmaf(w, gg[cc[pj]], a7[pj]);
        }
        float* zp = zpart + ks * 784 + ci_ * 7;
#pragma unroll
        for (int pj = 0; pj < 7; pj++) zp[pj] = a7[pj];
    }
    __syncthreads();

    // ---- combine halves + overlap-add scatter ----
    for (int d = tid; d < CI * 49; d += 256) {
        int c = d / 49, rem2 = d % 49, pi = rem2 / 7, pj = rem2 % 7;
        float val = (zpart[d] + zpart[784 + d]) * invs;
        int prr = clampi(qi + pi - 3, Hn - 1), pcc = clampi(qj + pj - 3, Wn - 1);
        atomicAdd(&g_zimg[(b * CI + c) * HWn + prr * Wn + pcc], val);
    }
}

// ------------------------- fused output: out = A*(zimg/cnt) + w_c33_r*vid + b2
__global__ void out_kernel(const float* __restrict__ vid,
                           const float* __restrict__ wc, float* __restrict__ out) {
    __shared__ float sA[CIN * CI], sW2[CIN * CIN], sB2[CIN];
    int tid = threadIdx.x;
    for (int i = tid; i < CIN * CI; i += 256) sA[i] = g_A[i];
    for (int i = tid; i < CIN * CIN; i += 256) {
        int o = i / CIN, c = i % CIN;
        sW2[i] = wc[o * (2 * CIN) + CIN + c];
    }
    if (tid < CIN) sB2[tid] = g_b2[tid];
    __syncthreads();

    int idx = blockIdx.x * 256 + tid;
    if (idx >= Bn * HWn * 4) return;
    int grp = idx / (Bn * HWn);
    int pix = idx % (Bn * HWn);
    int b = pix / HWn, hw = pix % HWn;

    float invc = 1.0f / fmaxf(g_cnt[hw], 1.0f);
    float zv[CI];
#pragma unroll
    for (int ci = 0; ci < CI; ci++) zv[ci] = g_zimg[(b * CI + ci) * HWn + hw] * invc;
    float x[CIN];
#pragma unroll
    for (int c = 0; c < CIN; c++) x[c] = vid[(b * CIN + c) * HWn + hw];

    int o0 = grp * 16;
#pragma unroll 4
    for (int oo = 0; oo < 16; oo++) {
        int o = o0 + oo;
        float a = sB2[o];
#pragma unroll
        for (int ci = 0; ci < CI; ci++) a = fmaf(sA[o * CI + ci], zv[ci], a);
#pragma unroll
        for (int c = 0; c < CIN; c++) a = fmaf(sW2[o * CIN + c], x[c], a);
        out[(b * CIN + o) * HWn + hw] = a;
    }
}

// ------------------------- launch --------------------------------------------
extern "C" void kernel_launch(void* const* d_in, const int* in_sizes, int n_in,
                              void* d_out, int out_size) {
    const float* vid = (const float*)d_in[0];
    const float* w_theta = (const float*)d_in[1];
    const float* b_theta = (const float*)d_in[2];
    const float* w_phi = (const float*)d_in[3];
    const float* b_phi = (const float*)d_in[4];
    const float* w_g = (const float*)d_in[5];
    const float* b_g = (const float*)d_in[6];
    const float* w_w = (const float*)d_in[7];
    const float* b_w = (const float*)d_in[8];
    const float* w_c33 = (const float*)d_in[9];
    const float* b_c33 = (const float*)d_in[10];
    float* out = (float*)d_out;

    int smem = SMEM_WORDS * 4;
    cudaFuncSetAttribute(attn_kernel, cudaFuncAttributeMaxDynamicSharedMemorySize, smem);

    zero_kernel<<<(Bn * CI * HWn + 255) / 256, 256>>>();
    proj_kernel<<<(Bn * HWn * 3 + 255) / 256, 256>>>(vid, w_theta, b_theta, w_phi, b_phi, w_g, b_g);
    precomp_kernel<<<4, 256>>>(w_w, b_w, w_c33, b_c33);
    attn_kernel<<<Bn * Qn, 256, smem>>>();
    out_kernel<<<(Bn * HWn * 4 + 255) / 256, 256>>>(vid, w_c33, out);
}